// round 4
// baseline (speedup 1.0000x reference)
#include <cuda_runtime.h>
#include <cuda_bf16.h>
#include <math.h>
#include <stdint.h>

// ---------------- problem constants ----------------
#define LSEQ 2048
#define DMODEL 768
#define KDIM 768
#define NHEAD 12
#define DHEAD 64
#define NCHUNK 16
#define CSIZE 128
#define LN_EPS 1e-5f
#define DEN_EPS 1e-6f

// ---------------- scratch (device globals) ----------------
__device__ __align__(128) __nv_bfloat16 g_ahi[LSEQ * DMODEL];   // LN(x) hi
__device__ __align__(128) __nv_bfloat16 g_alo[LSEQ * DMODEL];   // LN(x) lo
__device__ __align__(128) __nv_bfloat16 g_xhi[LSEQ * DMODEL];   // x hi
__device__ __align__(128) __nv_bfloat16 g_xlo[LSEQ * DMODEL];   // x lo
__device__ __align__(128) __nv_bfloat16 g_wqkv_hi[2304 * KDIM]; // W_qkv^T
__device__ __align__(128) __nv_bfloat16 g_wqkv_lo[2304 * KDIM];
__device__ __align__(128) __nv_bfloat16 g_wsc_hi[3072 * KDIM];  // [W_sem;W_ctx]^T
__device__ __align__(128) __nv_bfloat16 g_wsc_lo[3072 * KDIM];
__device__ __align__(128) __nv_bfloat16 g_wpr_hi[768 * KDIM];   // W_proj^T
__device__ __align__(128) __nv_bfloat16 g_wpr_lo[768 * KDIM];
__device__ __align__(128) __nv_bfloat16 g_athi[LSEQ * DMODEL];  // attn out hi
__device__ __align__(128) __nv_bfloat16 g_atlo[LSEQ * DMODEL];  // attn out lo
__device__ __align__(128) float g_bsc[3072];
__device__ __align__(128) float g_qkv[LSEQ * 3 * DMODEL];
__device__ __align__(128) float g_semctx[LSEQ * 3072];
__device__ float g_qf[NHEAD * LSEQ * DHEAD];
__device__ float g_kf[NHEAD * LSEQ * DHEAD];
__device__ float g_vv[NHEAD * LSEQ * DHEAD];
__device__ float g_S [NHEAD * NCHUNK * DHEAD * DHEAD];
__device__ float g_Z [NHEAD * NCHUNK * DHEAD];

// ---------------- PTX helpers (family-portable only) ----------------
__device__ __forceinline__ uint32_t smem_u32(const void* p) {
    uint32_t a;
    asm("{ .reg .u64 t; cvta.to.shared.u64 t, %1; cvt.u32.u64 %0, t; }" : "=r"(a) : "l"(p));
    return a;
}
__device__ __forceinline__ void cp_async16(uint32_t dst, const void* src) {
    asm volatile("cp.async.cg.shared.global [%0], [%1], 16;" :: "r"(dst), "l"(src));
}
__device__ __forceinline__ void cp_commit() {
    asm volatile("cp.async.commit_group;" ::: "memory");
}
__device__ __forceinline__ void cp_wait1() {
    asm volatile("cp.async.wait_group 1;" ::: "memory");
}
#define LDSM4(r0, r1, r2, r3, a) \
    asm volatile("ldmatrix.sync.aligned.m8n8.x4.shared.b16 {%0,%1,%2,%3}, [%4];" \
                 : "=r"(r0), "=r"(r1), "=r"(r2), "=r"(r3) : "r"(a))
#define MMA16816(d, a0, a1, a2, a3, b0, b1) \
    asm volatile("mma.sync.aligned.m16n8k16.row.col.f32.bf16.bf16.f32 " \
                 "{%0,%1,%2,%3}, {%4,%5,%6,%7}, {%8,%9}, {%0,%1,%2,%3};" \
                 : "+f"((d)[0]), "+f"((d)[1]), "+f"((d)[2]), "+f"((d)[3]) \
                 : "r"(a0), "r"(a1), "r"(a2), "r"(a3), "r"(b0), "r"(b1))

// ---------------- GEMM core (bf16x3 fused: AhiBhi + AhiBlo + AloBhi) ----------------
#define BK 32
#define ROWB 80
#define NKT (KDIM / BK)               // 24

// MT16: warp covers MT16 m16-tiles in M  ->  CTA tile = (MT16*32) x 128
template<int MT16>
__device__ __forceinline__ void g_load_stage(
    uint32_t smem_base, int s, int tid,
    const __nv_bfloat16* a0, const __nv_bfloat16* a1,
    const __nv_bfloat16* b0, const __nv_bfloat16* b1)
{
    constexpr int BM = MT16 * 32;
    constexpr uint32_t TILEA = BM * ROWB;
    constexpr uint32_t TILEBB = 128 * ROWB;
    constexpr uint32_t STAGE = 2 * TILEA + 2 * TILEBB;
    uint32_t stb = smem_base + (uint32_t)(s & 1) * STAGE;
    int kk = s * BK;
    #pragma unroll
    for (int t = 0; t < 2; t++) {
        const __nv_bfloat16* base = t ? a1 : a0;
        #pragma unroll
        for (int i = 0; i < BM * 4 / 256; i++) {
            int c = tid + i * 256;
            int r = c >> 2, seg = c & 3;
            cp_async16(stb + (uint32_t)t * TILEA + (uint32_t)(r * ROWB + seg * 16),
                       base + (size_t)r * KDIM + kk + seg * 8);
        }
    }
    #pragma unroll
    for (int t = 0; t < 2; t++) {
        const __nv_bfloat16* base = t ? b1 : b0;
        #pragma unroll
        for (int i = 0; i < 2; i++) {
            int c = tid + i * 256;
            int r = c >> 2, seg = c & 3;
            cp_async16(stb + 2 * TILEA + (uint32_t)t * TILEBB + (uint32_t)(r * ROWB + seg * 16),
                       base + (size_t)r * KDIM + kk + seg * 8);
        }
    }
}

template<int MT16>
__device__ __forceinline__ void gemm_body(
    const __nv_bfloat16* __restrict__ Ahi, const __nv_bfloat16* __restrict__ Alo,
    const __nv_bfloat16* __restrict__ BhiT, const __nv_bfloat16* __restrict__ BloT,
    const float* __restrict__ bias, float* __restrict__ C, int Ntot,
    int bx, int by, char* smem)
{
    constexpr int BM = MT16 * 32;
    constexpr uint32_t TILEA = BM * ROWB;
    constexpr uint32_t TILEBB = 128 * ROWB;
    constexpr uint32_t STAGE = 2 * TILEA + 2 * TILEBB;

    const int tid = threadIdx.x;
    const int wid = tid >> 5;
    const int lane = tid & 31;
    const int wm = wid & 1;
    const int wn = wid >> 1;

    uint32_t smem_base = smem_u32(smem);

    const __nv_bfloat16* a0 = Ahi + (size_t)by * BM * KDIM;
    const __nv_bfloat16* a1 = Alo + (size_t)by * BM * KDIM;
    const __nv_bfloat16* b0 = BhiT + (size_t)bx * 128 * KDIM;
    const __nv_bfloat16* b1 = BloT + (size_t)bx * 128 * KDIM;

    float acc[MT16][4][4];
    #pragma unroll
    for (int i = 0; i < MT16; i++)
        #pragma unroll
        for (int j = 0; j < 4; j++)
            #pragma unroll
            for (int t = 0; t < 4; t++) acc[i][j][t] = 0.f;

    const uint32_t a_row = (uint32_t)(lane & 15);
    const uint32_t a_byt = (uint32_t)((lane >> 4) * 16);
    const uint32_t b_row = (uint32_t)((lane & 7) + ((lane >> 4) << 3));
    const uint32_t b_byt = (uint32_t)(((lane >> 3) & 1) * 16);

    g_load_stage<MT16>(smem_base, 0, tid, a0, a1, b0, b1);
    cp_commit();

    for (int s = 0; s < NKT; s++) {
        if (s + 1 < NKT) g_load_stage<MT16>(smem_base, s + 1, tid, a0, a1, b0, b1);
        cp_commit();
        cp_wait1();
        __syncthreads();

        uint32_t stb = smem_base + (uint32_t)(s & 1) * STAGE;
        #pragma unroll
        for (int pass = 0; pass < 3; pass++) {
            uint32_t At = stb + ((pass < 2) ? 0u : TILEA);
            uint32_t Bt = stb + 2 * TILEA + ((pass == 1) ? TILEBB : 0u);
            #pragma unroll
            for (int k16 = 0; k16 < 2; k16++) {
                uint32_t a[MT16][4];
                #pragma unroll
                for (int mt = 0; mt < MT16; mt++) {
                    uint32_t addr = At + (uint32_t)(wm * (MT16 * 16) + mt * 16 + a_row) * ROWB
                                  + (uint32_t)(k16 * 32) + a_byt;
                    LDSM4(a[mt][0], a[mt][1], a[mt][2], a[mt][3], addr);
                }
                uint32_t b[2][4];
                #pragma unroll
                for (int nb = 0; nb < 2; nb++) {
                    uint32_t addr = Bt + (uint32_t)(wn * 32 + nb * 16 + b_row) * ROWB
                                  + (uint32_t)(k16 * 32) + b_byt;
                    LDSM4(b[nb][0], b[nb][1], b[nb][2], b[nb][3], addr);
                }
                #pragma unroll
                for (int mt = 0; mt < MT16; mt++)
                    #pragma unroll
                    for (int nt = 0; nt < 4; nt++)
                        MMA16816(acc[mt][nt],
                                 a[mt][0], a[mt][1], a[mt][2], a[mt][3],
                                 b[nt >> 1][(nt & 1) * 2], b[nt >> 1][(nt & 1) * 2 + 1]);
            }
        }
        __syncthreads();
    }

    int r0 = by * BM + wm * (MT16 * 16) + (lane >> 2);
    int c0 = bx * 128 + wn * 32 + (lane & 3) * 2;
    #pragma unroll
    for (int mt = 0; mt < MT16; mt++) {
        #pragma unroll
        for (int nt = 0; nt < 4; nt++) {
            int r = r0 + mt * 16;
            int c = c0 + nt * 8;
            float2 v0 = { acc[mt][nt][0] + bias[c], acc[mt][nt][1] + bias[c + 1] };
            float2 v1 = { acc[mt][nt][2] + bias[c], acc[mt][nt][3] + bias[c + 1] };
            *(float2*)&C[(size_t)r * Ntot + c] = v0;
            *(float2*)&C[(size_t)(r + 8) * Ntot + c] = v1;
        }
    }
}

// merged qkv + sem/ctx GEMM: grid (18 + 24, 16)
__global__ __launch_bounds__(256, 2)
void gemm_big(const float* __restrict__ bias_qkv)
{
    extern __shared__ __align__(128) char smem[];
    int bx = blockIdx.x;
    if (bx < 18)
        gemm_body<4>(g_ahi, g_alo, g_wqkv_hi, g_wqkv_lo, bias_qkv, g_qkv, 2304,
                     bx, blockIdx.y, smem);
    else
        gemm_body<4>(g_xhi, g_xlo, g_wsc_hi, g_wsc_lo, g_bsc, g_semctx, 3072,
                     bx - 18, blockIdx.y, smem);
}
#define GEMM_SMEM_BIG (2 * (2 * 128 * ROWB + 2 * 128 * ROWB))

// proj GEMM: BM=64 tiles, grid (6, 32)
__global__ __launch_bounds__(256, 2)
void gemm_proj(const float* __restrict__ bias, float* __restrict__ C)
{
    extern __shared__ __align__(128) char smem[];
    gemm_body<2>(g_athi, g_atlo, g_wpr_hi, g_wpr_lo, bias, C, 768,
                 blockIdx.x, blockIdx.y, smem);
}
#define GEMM_SMEM_PROJ (2 * (2 * 64 * ROWB + 2 * 128 * ROWB))

// ---------------- merged weight transpose + bf16 split (one launch) ----------------
// bx < 72: W_qkv (N=2304) -> g_wqkv;  < 120: W_sem -> g_wsc[0:1536];
// < 168: W_ctx -> g_wsc[1536:3072];  < 192: W_proj -> g_wpr
__global__ void transpose_split_all(const float* __restrict__ Wq,
                                    const float* __restrict__ Ws,
                                    const float* __restrict__ Wc,
                                    const float* __restrict__ Wp)
{
    __shared__ float tile[32][33];
    int bx = blockIdx.x;
    const float* W; int N, rowOff;
    __nv_bfloat16 *hiT, *loT;
    if (bx < 72)       { W = Wq; N = 2304; rowOff = 0;    hiT = g_wqkv_hi; loT = g_wqkv_lo; }
    else if (bx < 120) { W = Ws; N = 1536; rowOff = 0;    hiT = g_wsc_hi;  loT = g_wsc_lo;  bx -= 72; }
    else if (bx < 168) { W = Wc; N = 1536; rowOff = 1536; hiT = g_wsc_hi;  loT = g_wsc_lo;  bx -= 120; }
    else               { W = Wp; N = 768;  rowOff = 0;    hiT = g_wpr_hi;  loT = g_wpr_lo;  bx -= 168; }

    int n0 = bx * 32, k0 = blockIdx.y * 32;
    int tx = threadIdx.x, ty = threadIdx.y;   // (32, 8)
    #pragma unroll
    for (int i = 0; i < 4; i++)
        tile[ty + i * 8][tx] = W[(size_t)(k0 + ty + i * 8) * N + n0 + tx];
    __syncthreads();
    #pragma unroll
    for (int i = 0; i < 4; i++) {
        int n = ty + i * 8;
        float v = tile[tx][n];
        __nv_bfloat16 h = __float2bfloat16(v);
        __nv_bfloat16 l = __float2bfloat16(v - __bfloat162float(h));
        size_t o = (size_t)(rowOff + n0 + n) * KDIM + k0 + tx;
        hiT[o] = h;
        loT[o] = l;
    }
}

__global__ void concat_bias(const float* __restrict__ bs, const float* __restrict__ bc) {
    int i = blockIdx.x * 256 + threadIdx.x;
    if (i < 1536) g_bsc[i] = bs[i];
    else if (i < 3072) g_bsc[i] = bc[i - 1536];
}

// ---------------- LayerNorm + split (also splits raw x) ----------------
__global__ void ln_split_kernel(const float* __restrict__ x,
                                const float* __restrict__ gamma,
                                const float* __restrict__ beta) {
    int row = blockIdx.x;
    const float* xr = x + (size_t)row * DMODEL;
    int tid = threadIdx.x;
    __shared__ float red[8];

    float s = 0.f;
    for (int i = tid; i < DMODEL; i += 256) s += xr[i];
    #pragma unroll
    for (int o = 16; o > 0; o >>= 1) s += __shfl_down_sync(0xffffffffu, s, o);
    if ((tid & 31) == 0) red[tid >> 5] = s;
    __syncthreads();
    if (tid < 8) {
        s = red[tid];
        #pragma unroll
        for (int o = 4; o > 0; o >>= 1) s += __shfl_down_sync(0xffu, s, o);
        if (tid == 0) red[0] = s;
    }
    __syncthreads();
    float mu = red[0] * (1.f / DMODEL);
    __syncthreads();

    float v = 0.f;
    for (int i = tid; i < DMODEL; i += 256) { float d = xr[i] - mu; v += d * d; }
    #pragma unroll
    for (int o = 16; o > 0; o >>= 1) v += __shfl_down_sync(0xffffffffu, v, o);
    if ((tid & 31) == 0) red[tid >> 5] = v;
    __syncthreads();
    if (tid < 8) {
        v = red[tid];
        #pragma unroll
        for (int o = 4; o > 0; o >>= 1) v += __shfl_down_sync(0xffu, v, o);
        if (tid == 0) red[0] = v;
    }
    __syncthreads();
    float inv = rsqrtf(red[0] * (1.f / DMODEL) + LN_EPS);

    for (int i = tid; i < DMODEL; i += 256) {
        float xv = xr[i];
        float ln = (xv - mu) * inv * gamma[i] + beta[i];
        __nv_bfloat16 h = __float2bfloat16(ln);
        g_ahi[(size_t)row * DMODEL + i] = h;
        g_alo[(size_t)row * DMODEL + i] = __float2bfloat16(ln - __bfloat162float(h));
        __nv_bfloat16 xh = __float2bfloat16(xv);
        g_xhi[(size_t)row * DMODEL + i] = xh;
        g_xlo[(size_t)row * DMODEL + i] = __float2bfloat16(xv - __bfloat162float(xh));
    }
}

// ---------------- gate + feature map (fast-math intrinsics) ----------------
__device__ __forceinline__ float softplus_fast(float x) {
    // x>0: x + log(1+e^-x); else log(1+e^x). args to __logf in (1,2] -> accurate.
    return (x > 0.f) ? x + __logf(1.f + __expf(-x)) : __logf(1.f + __expf(x));
}

__global__ void features_kernel() {
    int idx = blockIdx.x * blockDim.x + threadIdx.x;
    if (idx >= LSEQ * DMODEL) return;
    int l = idx / DMODEL;
    int d = idx - l * DMODEL;

    const float* scr = g_semctx + (size_t)l * 3072;
    float sa = softplus_fast(scr[d]);
    float sp = scr[768 + d];
    float ca = softplus_fast(scr[1536 + d]);
    float cp = scr[2304 + d];
    float z = sa * ca * __cosf(sp - cp);
    float gate = 1.f / (1.f + __expf(-z));

    float q = g_qkv[(size_t)l * 3 * DMODEL + d];
    float k = g_qkv[(size_t)l * 3 * DMODEL + DMODEL + d] * gate;
    float v = g_qkv[(size_t)l * 3 * DMODEL + 2 * DMODEL + d];

    int h = d >> 6;
    int dh = d & 63;
    size_t o = (size_t)h * LSEQ * DHEAD + (size_t)l * DHEAD + dh;
    g_qf[o] = (q > 0.f) ? q + 1.f : __expf(q);
    g_kf[o] = (k > 0.f) ? k + 1.f : __expf(k);
    g_vv[o] = v;
}

// ---------------- phase A: per-chunk state sums ----------------
__global__ __launch_bounds__(256)
void chunk_sums_kernel() {
    int h = blockIdx.x / NCHUNK;
    int c = blockIdx.x % NCHUNK;
    const float* Kb = g_kf + (size_t)h * LSEQ * DHEAD + (size_t)c * CSIZE * DHEAD;
    const float* Vb = g_vv + (size_t)h * LSEQ * DHEAD + (size_t)c * CSIZE * DHEAD;

    __shared__ float ks[16][64];
    __shared__ float vs[16][64];
    int tid = threadIdx.x;
    int te = tid & 15;
    int td = tid >> 4;

    float acc[4][4];
    #pragma unroll
    for (int i = 0; i < 4; i++)
        #pragma unroll
        for (int j = 0; j < 4; j++) acc[i][j] = 0.f;
    float zacc[4] = {0.f, 0.f, 0.f, 0.f};

    int lr = tid >> 4;
    int lc = (tid & 15) * 4;

    for (int p0 = 0; p0 < CSIZE; p0 += 16) {
        *(float4*)&ks[lr][lc] = *(const float4*)&Kb[(size_t)(p0 + lr) * DHEAD + lc];
        *(float4*)&vs[lr][lc] = *(const float4*)&Vb[(size_t)(p0 + lr) * DHEAD + lc];
        __syncthreads();
        #pragma unroll
        for (int p = 0; p < 16; p++) {
            float kk[4], vvv[4];
            #pragma unroll
            for (int i = 0; i < 4; i++) kk[i] = ks[p][td * 4 + i];
            #pragma unroll
            for (int j = 0; j < 4; j++) vvv[j] = vs[p][te * 4 + j];
            #pragma unroll
            for (int i = 0; i < 4; i++)
                #pragma unroll
                for (int j = 0; j < 4; j++)
                    acc[i][j] = fmaf(kk[i], vvv[j], acc[i][j]);
            if (te == 0) {
                #pragma unroll
                for (int i = 0; i < 4; i++) zacc[i] += kk[i];
            }
        }
        __syncthreads();
    }

    float* Sb = g_S + (size_t)(h * NCHUNK + c) * DHEAD * DHEAD;
    #pragma unroll
    for (int i = 0; i < 4; i++)
        #pragma unroll
        for (int j = 0; j < 4; j++)
            Sb[(size_t)(td * 4 + i) * DHEAD + te * 4 + j] = acc[i][j];
    if (te == 0) {
        float* Zb = g_Z + (size_t)(h * NCHUNK + c) * DHEAD;
        #pragma unroll
        for (int i = 0; i < 4; i++) Zb[td * 4 + i] = zacc[i];
    }
}

// ---------------- phase B: exclusive scan over chunks (grid (12,4)) ----------------
__global__ __launch_bounds__(256)
void scan_states_kernel() {
    int h = blockIdx.x;
    int part = blockIdx.y;
    int tid = threadIdx.x;
    float pref[4] = {0.f, 0.f, 0.f, 0.f};
    float prefz = 0.f;

    for (int c = 0; c < NCHUNK; c++) {
        float* Sb = g_S + (size_t)(h * NCHUNK + c) * DHEAD * DHEAD + part * 1024;
        #pragma unroll
        for (int i = 0; i < 4; i++) {
            int idx = tid + i * 256;
            float cur = Sb[idx];
            Sb[idx] = pref[i];
            pref[i] += cur;
        }
        if (part == 0 && tid < DHEAD) {
            float* Zb = g_Z + (size_t)(h * NCHUNK + c) * DHEAD;
            float cur = Zb[tid];
            Zb[tid] = prefz;
            prefz += cur;
        }
    }
}

// ---------------- phase C: per-chunk causal output + bf16 split ----------------
#define SMEM_C ((2 * CSIZE * DHEAD + DHEAD * DHEAD + DHEAD) * 4)

__global__ __launch_bounds__(128)
void chunk_attn_kernel() {
    int h = blockIdx.x / NCHUNK;
    int c = blockIdx.x % NCHUNK;
    extern __shared__ float sh[];
    float* Ks = sh;
    float* Vs = Ks + CSIZE * DHEAD;
    float* Ps = Vs + CSIZE * DHEAD;
    float* Zs = Ps + DHEAD * DHEAD;

    int tid = threadIdx.x;
    size_t base = (size_t)h * LSEQ * DHEAD + (size_t)c * CSIZE * DHEAD;

    const float4* Kg = (const float4*)(g_kf + base);
    const float4* Vg = (const float4*)(g_vv + base);
    for (int j = tid; j < CSIZE * DHEAD / 4; j += 128) {
        ((float4*)Ks)[j] = Kg[j];
        ((float4*)Vs)[j] = Vg[j];
    }
    const float4* Pg = (const float4*)(g_S + (size_t)(h * NCHUNK + c) * DHEAD * DHEAD);
    for (int j = tid; j < DHEAD * DHEAD / 4; j += 128) ((float4*)Ps)[j] = Pg[j];
    const float4* Zg = (const float4*)(g_Z + (size_t)(h * NCHUNK + c) * DHEAD);
    if (tid < DHEAD / 4) ((float4*)Zs)[tid] = Zg[tid];
    __syncthreads();

    float q[DHEAD];
    {
        const float4* qp = (const float4*)(g_qf + base + (size_t)tid * DHEAD);
        #pragma unroll
        for (int i = 0; i < DHEAD / 4; i++) {
            float4 t = qp[i];
            q[4 * i + 0] = t.x; q[4 * i + 1] = t.y; q[4 * i + 2] = t.z; q[4 * i + 3] = t.w;
        }
    }

    float out[DHEAD];
    float den = 0.f;
    #pragma unroll
    for (int d = 0; d < DHEAD; d++) den = fmaf(q[d], Zs[d], den);
    #pragma unroll
    for (int e = 0; e < DHEAD; e++) out[e] = 0.f;
    #pragma unroll 8
    for (int d = 0; d < DHEAD; d++) {
        float qd = q[d];
        #pragma unroll
        for (int e = 0; e < DHEAD; e++)
            out[e] = fmaf(qd, Ps[d * DHEAD + e], out[e]);
    }

    for (int j = 0; j <= tid; j++) {
        float s = 0.f;
        const float4* kr = (const float4*)(Ks + j * DHEAD);
        #pragma unroll
        for (int i = 0; i < DHEAD / 4; i++) {
            float4 kv = kr[i];
            s = fmaf(q[4 * i + 0], kv.x, s);
            s = fmaf(q[4 * i + 1], kv.y, s);
            s = fmaf(q[4 * i + 2], kv.z, s);
            s = fmaf(q[4 * i + 3], kv.w, s);
        }
        den += s;
        const float4* vr = (const float4*)(Vs + j * DHEAD);
        #pragma unroll
        for (int i = 0; i < DHEAD / 4; i++) {
            float4 vv4 = vr[i];
            out[4 * i + 0] = fmaf(s, vv4.x, out[4 * i + 0]);
            out[4 * i + 1] = fmaf(s, vv4.y, out[4 * i + 1]);
            out[4 * i + 2] = fmaf(s, vv4.z, out[4 * i + 2]);
            out[4 * i + 3] = fmaf(s, vv4.w, out[4 * i + 3]);
        }
    }

    float inv = 1.f / (den + DEN_EPS);
    int l = c * CSIZE + tid;
    __nv_bfloat16* oh = g_athi + (size_t)l * DMODEL + h * DHEAD;
    __nv_bfloat16* ol = g_atlo + (size_t)l * DMODEL + h * DHEAD;
    #pragma unroll
    for (int e = 0; e < DHEAD; e++) {
        float v = out[e] * inv;
        __nv_bfloat16 hh = __float2bfloat16(v);
        oh[e] = hh;
        ol[e] = __float2bfloat16(v - __bfloat162float(hh));
    }
}

// ---------------- host launcher ----------------
extern "C" void kernel_launch(void* const* d_in, const int* in_sizes, int n_in,
                              void* d_out, int out_size) {
    const float* x      = (const float*)d_in[0];
    const float* W_qkv  = (const float*)d_in[1];
    const float* b_qkv  = (const float*)d_in[2];
    const float* W_sem  = (const float*)d_in[3];
    const float* b_sem  = (const float*)d_in[4];
    const float* W_ctx  = (const float*)d_in[5];
    const float* b_ctx  = (const float*)d_in[6];
    const float* W_proj = (const float*)d_in[7];
    const float* b_proj = (const float*)d_in[8];
    const float* ln_g   = (const float*)d_in[9];
    const float* ln_b   = (const float*)d_in[10];
    float* out = (float*)d_out;

    cudaFuncSetAttribute(gemm_big, cudaFuncAttributeMaxDynamicSharedMemorySize, GEMM_SMEM_BIG);
    cudaFuncSetAttribute(gemm_proj, cudaFuncAttributeMaxDynamicSharedMemorySize, GEMM_SMEM_PROJ);
    cudaFuncSetAttribute(chunk_attn_kernel, cudaFuncAttributeMaxDynamicSharedMemorySize, SMEM_C);

    // weight prep (single launch) + biases + LN
    transpose_split_all<<<dim3(192, 24), dim3(32, 8)>>>(W_qkv, W_sem, W_ctx, W_proj);
    concat_bias<<<12, 256>>>(b_sem, b_ctx);
    ln_split_kernel<<<LSEQ, 256>>>(x, ln_g, ln_b);

    // merged tensor-core GEMMs (qkv + sem/ctx)
    gemm_big<<<dim3(42, 16), 256, GEMM_SMEM_BIG>>>(b_qkv);

    // gate + feature map
    features_kernel<<<(LSEQ * DMODEL + 255) / 256, 256>>>();

    // chunked linear attention
    chunk_sums_kernel<<<NHEAD * NCHUNK, 256>>>();
    scan_states_kernel<<<dim3(NHEAD, 4), 256>>>();
    chunk_attn_kernel<<<NHEAD * NCHUNK, 128, SMEM_C>>>();

    // output projection (BM=64 tiles for occupancy)
    gemm_proj<<<dim3(6, 32), 256, GEMM_SMEM_PROJ>>>(b_proj, out);
}

// round 5
// speedup vs baseline: 1.5307x; 1.5307x over previous
#include <cuda_runtime.h>
#include <cuda_bf16.h>
#include <math.h>
#include <stdint.h>

// ---------------- problem constants ----------------
#define LSEQ 2048
#define DMODEL 768
#define KDIM 768
#define NHEAD 12
#define DHEAD 64
#define NCHUNK 16
#define CSIZE 128
#define LN_EPS 1e-5f
#define DEN_EPS 1e-6f

// ---------------- scratch (device globals) ----------------
__device__ __align__(128) __nv_bfloat16 g_ahi[LSEQ * DMODEL];   // LN(x) hi
__device__ __align__(128) __nv_bfloat16 g_alo[LSEQ * DMODEL];   // LN(x) lo
__device__ __align__(128) __nv_bfloat16 g_xhi[LSEQ * DMODEL];   // x hi
__device__ __align__(128) __nv_bfloat16 g_xlo[LSEQ * DMODEL];   // x lo
__device__ __align__(128) __nv_bfloat16 g_wqkv_hi[2304 * KDIM]; // W_qkv^T
__device__ __align__(128) __nv_bfloat16 g_wqkv_lo[2304 * KDIM];
__device__ __align__(128) __nv_bfloat16 g_wsc_hi[3072 * KDIM];  // [W_sem;W_ctx]^T
__device__ __align__(128) __nv_bfloat16 g_wsc_lo[3072 * KDIM];
__device__ __align__(128) __nv_bfloat16 g_wpr_hi[768 * KDIM];   // W_proj^T
__device__ __align__(128) __nv_bfloat16 g_wpr_lo[768 * KDIM];
__device__ __align__(128) __nv_bfloat16 g_athi[LSEQ * DMODEL];  // attn out hi
__device__ __align__(128) __nv_bfloat16 g_atlo[LSEQ * DMODEL];  // attn out lo
__device__ __align__(128) float g_bsc[3072];
__device__ __align__(128) float g_qkv[LSEQ * 3 * DMODEL];
__device__ __align__(128) float g_semctx[LSEQ * 3072];
__device__ float g_qf[NHEAD * LSEQ * DHEAD];
__device__ float g_kf[NHEAD * LSEQ * DHEAD];
__device__ float g_vv[NHEAD * LSEQ * DHEAD];
__device__ float g_S [NHEAD * NCHUNK * DHEAD * DHEAD];
__device__ float g_Z [NHEAD * NCHUNK * DHEAD];

// ---------------- PTX helpers (family-portable only) ----------------
__device__ __forceinline__ uint32_t smem_u32(const void* p) {
    uint32_t a;
    asm("{ .reg .u64 t; cvta.to.shared.u64 t, %1; cvt.u32.u64 %0, t; }" : "=r"(a) : "l"(p));
    return a;
}
__device__ __forceinline__ void cp_async16(uint32_t dst, const void* src) {
    asm volatile("cp.async.cg.shared.global [%0], [%1], 16;" :: "r"(dst), "l"(src));
}
__device__ __forceinline__ void cp_commit() {
    asm volatile("cp.async.commit_group;" ::: "memory");
}
__device__ __forceinline__ void cp_wait1() {
    asm volatile("cp.async.wait_group 1;" ::: "memory");
}
#define LDSM4(r0, r1, r2, r3, a) \
    asm volatile("ldmatrix.sync.aligned.m8n8.x4.shared.b16 {%0,%1,%2,%3}, [%4];" \
                 : "=r"(r0), "=r"(r1), "=r"(r2), "=r"(r3) : "r"(a))
#define MMA16816(d, a0, a1, a2, a3, b0, b1) \
    asm volatile("mma.sync.aligned.m16n8k16.row.col.f32.bf16.bf16.f32 " \
                 "{%0,%1,%2,%3}, {%4,%5,%6,%7}, {%8,%9}, {%0,%1,%2,%3};" \
                 : "+f"((d)[0]), "+f"((d)[1]), "+f"((d)[2]), "+f"((d)[3]) \
                 : "r"(a0), "r"(a1), "r"(a2), "r"(a3), "r"(b0), "r"(b1))

// ---------------- GEMM: C[2048,Ntot] = A @ B^T + bias (bf16x3 fused) ----------------
// C = Ahi*Bhi + Ahi*Blo + Alo*Bhi, fp32 accum. Frag-sharing inner loop.
#define BK 32
#define ROWB 80                       // padded smem row stride (bytes) -> conflict-free
#define TILEB (128 * ROWB)            // 10240 B per 128x32 tile
#define STAGEB (4 * TILEB)            // Ahi, Alo, Bhi, Blo
#define NSTAGE 2
#define GEMM_SMEM (NSTAGE * STAGEB)   // 81920 B
#define NKT (KDIM / BK)               // 24

__device__ __forceinline__ void g_load_stage(
    uint32_t smem_base, int s, int tid,
    const __nv_bfloat16* a0, const __nv_bfloat16* a1,
    const __nv_bfloat16* b0, const __nv_bfloat16* b1)
{
    uint32_t stb = smem_base + (uint32_t)(s & (NSTAGE - 1)) * STAGEB;
    int kk = s * BK;
    #pragma unroll
    for (int t = 0; t < 4; t++) {
        const __nv_bfloat16* base = (t == 0) ? a0 : (t == 1) ? a1 : (t == 2) ? b0 : b1;
        #pragma unroll
        for (int i = 0; i < 2; i++) {
            int c = tid + i * 256;          // 0..511
            int r = c >> 2;
            int seg = c & 3;
            cp_async16(stb + (uint32_t)t * TILEB + (uint32_t)(r * ROWB + seg * 16),
                       base + (size_t)r * KDIM + kk + seg * 8);
        }
    }
}

__global__ __launch_bounds__(256, 2)
void gemm_mma(const __nv_bfloat16* __restrict__ Ahi, const __nv_bfloat16* __restrict__ Alo,
              const __nv_bfloat16* __restrict__ BhiT, const __nv_bfloat16* __restrict__ BloT,
              const float* __restrict__ bias, float* __restrict__ C, int Ntot)
{
    extern __shared__ __align__(128) char smem[];
    const int tid = threadIdx.x;
    const int wid = tid >> 5;
    const int lane = tid & 31;
    const int wm = wid & 1;        // M: 2 x 64
    const int wn = wid >> 1;       // N: 4 x 32
    const int bx = blockIdx.x, by = blockIdx.y;

    uint32_t smem_base = smem_u32(smem);

    const __nv_bfloat16* a0 = Ahi + (size_t)by * 128 * KDIM;
    const __nv_bfloat16* a1 = Alo + (size_t)by * 128 * KDIM;
    const __nv_bfloat16* b0 = BhiT + (size_t)bx * 128 * KDIM;
    const __nv_bfloat16* b1 = BloT + (size_t)bx * 128 * KDIM;

    float acc[4][4][4];
    #pragma unroll
    for (int i = 0; i < 4; i++)
        #pragma unroll
        for (int j = 0; j < 4; j++)
            #pragma unroll
            for (int t = 0; t < 4; t++) acc[i][j][t] = 0.f;

    const uint32_t a_row = (uint32_t)(lane & 15);
    const uint32_t a_byt = (uint32_t)((lane >> 4) * 16);
    const uint32_t b_row = (uint32_t)((lane & 7) + ((lane >> 4) << 3));
    const uint32_t b_byt = (uint32_t)(((lane >> 3) & 1) * 16);

    g_load_stage(smem_base, 0, tid, a0, a1, b0, b1);
    cp_commit();

    for (int s = 0; s < NKT; s++) {
        if (s + 1 < NKT) g_load_stage(smem_base, s + 1, tid, a0, a1, b0, b1);
        cp_commit();
        cp_wait1();
        __syncthreads();

        uint32_t stb = smem_base + (uint32_t)(s & (NSTAGE - 1)) * STAGEB;
        #pragma unroll
        for (int k16 = 0; k16 < 2; k16++) {
            const uint32_t koff = (uint32_t)(k16 * 32);
            // load Ahi, Bhi, Blo fragments once
            uint32_t ah[4][4];
            #pragma unroll
            for (int mt = 0; mt < 4; mt++) {
                uint32_t addr = stb + (uint32_t)(wm * 64 + mt * 16 + a_row) * ROWB
                              + koff + a_byt;
                LDSM4(ah[mt][0], ah[mt][1], ah[mt][2], ah[mt][3], addr);
            }
            uint32_t bh[2][4], bl[2][4];
            #pragma unroll
            for (int nb = 0; nb < 2; nb++) {
                uint32_t addr = stb + 2u * TILEB + (uint32_t)(wn * 32 + nb * 16 + b_row) * ROWB
                              + koff + b_byt;
                LDSM4(bh[nb][0], bh[nb][1], bh[nb][2], bh[nb][3], addr);
                LDSM4(bl[nb][0], bl[nb][1], bl[nb][2], bl[nb][3], addr + TILEB);
            }
            // pass 1: Ahi*Bhi, pass 2: Ahi*Blo (shares A frags)
            #pragma unroll
            for (int mt = 0; mt < 4; mt++)
                #pragma unroll
                for (int nt = 0; nt < 4; nt++)
                    MMA16816(acc[mt][nt],
                             ah[mt][0], ah[mt][1], ah[mt][2], ah[mt][3],
                             bh[nt >> 1][(nt & 1) * 2], bh[nt >> 1][(nt & 1) * 2 + 1]);
            #pragma unroll
            for (int mt = 0; mt < 4; mt++)
                #pragma unroll
                for (int nt = 0; nt < 4; nt++)
                    MMA16816(acc[mt][nt],
                             ah[mt][0], ah[mt][1], ah[mt][2], ah[mt][3],
                             bl[nt >> 1][(nt & 1) * 2], bl[nt >> 1][(nt & 1) * 2 + 1]);
            // pass 3: Alo*Bhi (reuses B-hi frags; A regs recycled)
            uint32_t al[4][4];
            #pragma unroll
            for (int mt = 0; mt < 4; mt++) {
                uint32_t addr = stb + TILEB + (uint32_t)(wm * 64 + mt * 16 + a_row) * ROWB
                              + koff + a_byt;
                LDSM4(al[mt][0], al[mt][1], al[mt][2], al[mt][3], addr);
            }
            #pragma unroll
            for (int mt = 0; mt < 4; mt++)
                #pragma unroll
                for (int nt = 0; nt < 4; nt++)
                    MMA16816(acc[mt][nt],
                             al[mt][0], al[mt][1], al[mt][2], al[mt][3],
                             bh[nt >> 1][(nt & 1) * 2], bh[nt >> 1][(nt & 1) * 2 + 1]);
        }
        __syncthreads();
    }

    int r0 = by * 128 + wm * 64 + (lane >> 2);
    int c0 = bx * 128 + wn * 32 + (lane & 3) * 2;
    #pragma unroll
    for (int mt = 0; mt < 4; mt++) {
        #pragma unroll
        for (int nt = 0; nt < 4; nt++) {
            int r = r0 + mt * 16;
            int c = c0 + nt * 8;
            float2 v0 = { acc[mt][nt][0] + bias[c], acc[mt][nt][1] + bias[c + 1] };
            float2 v1 = { acc[mt][nt][2] + bias[c], acc[mt][nt][3] + bias[c + 1] };
            *(float2*)&C[(size_t)r * Ntot + c] = v0;
            *(float2*)&C[(size_t)(r + 8) * Ntot + c] = v1;
        }
    }
}

// ---------------- merged weight transpose + bf16 split (one launch) ----------------
__global__ void transpose_split_all(const float* __restrict__ Wq,
                                    const float* __restrict__ Ws,
                                    const float* __restrict__ Wc,
                                    const float* __restrict__ Wp)
{
    __shared__ float tile[32][33];
    int bx = blockIdx.x;
    const float* W; int N, rowOff;
    __nv_bfloat16 *hiT, *loT;
    if (bx < 72)       { W = Wq; N = 2304; rowOff = 0;    hiT = g_wqkv_hi; loT = g_wqkv_lo; }
    else if (bx < 120) { W = Ws; N = 1536; rowOff = 0;    hiT = g_wsc_hi;  loT = g_wsc_lo;  bx -= 72; }
    else if (bx < 168) { W = Wc; N = 1536; rowOff = 1536; hiT = g_wsc_hi;  loT = g_wsc_lo;  bx -= 120; }
    else               { W = Wp; N = 768;  rowOff = 0;    hiT = g_wpr_hi;  loT = g_wpr_lo;  bx -= 168; }

    int n0 = bx * 32, k0 = blockIdx.y * 32;
    int tx = threadIdx.x, ty = threadIdx.y;   // (32, 8)
    #pragma unroll
    for (int i = 0; i < 4; i++)
        tile[ty + i * 8][tx] = W[(size_t)(k0 + ty + i * 8) * N + n0 + tx];
    __syncthreads();
    #pragma unroll
    for (int i = 0; i < 4; i++) {
        int n = ty + i * 8;
        float v = tile[tx][n];
        __nv_bfloat16 h = __float2bfloat16(v);
        __nv_bfloat16 l = __float2bfloat16(v - __bfloat162float(h));
        size_t o = (size_t)(rowOff + n0 + n) * KDIM + k0 + tx;
        hiT[o] = h;
        loT[o] = l;
    }
}

__global__ void concat_bias(const float* __restrict__ bs, const float* __restrict__ bc) {
    int i = blockIdx.x * 256 + threadIdx.x;
    if (i < 1536) g_bsc[i] = bs[i];
    else if (i < 3072) g_bsc[i] = bc[i - 1536];
}

// ---------------- LayerNorm + split (also splits raw x) ----------------
__global__ void ln_split_kernel(const float* __restrict__ x,
                                const float* __restrict__ gamma,
                                const float* __restrict__ beta) {
    int row = blockIdx.x;
    const float* xr = x + (size_t)row * DMODEL;
    int tid = threadIdx.x;
    __shared__ float red[8];

    float s = 0.f;
    for (int i = tid; i < DMODEL; i += 256) s += xr[i];
    #pragma unroll
    for (int o = 16; o > 0; o >>= 1) s += __shfl_down_sync(0xffffffffu, s, o);
    if ((tid & 31) == 0) red[tid >> 5] = s;
    __syncthreads();
    if (tid < 8) {
        s = red[tid];
        #pragma unroll
        for (int o = 4; o > 0; o >>= 1) s += __shfl_down_sync(0xffu, s, o);
        if (tid == 0) red[0] = s;
    }
    __syncthreads();
    float mu = red[0] * (1.f / DMODEL);
    __syncthreads();

    float v = 0.f;
    for (int i = tid; i < DMODEL; i += 256) { float d = xr[i] - mu; v += d * d; }
    #pragma unroll
    for (int o = 16; o > 0; o >>= 1) v += __shfl_down_sync(0xffffffffu, v, o);
    if ((tid & 31) == 0) red[tid >> 5] = v;
    __syncthreads();
    if (tid < 8) {
        v = red[tid];
        #pragma unroll
        for (int o = 4; o > 0; o >>= 1) v += __shfl_down_sync(0xffu, v, o);
        if (tid == 0) red[0] = v;
    }
    __syncthreads();
    float inv = rsqrtf(red[0] * (1.f / DMODEL) + LN_EPS);

    for (int i = tid; i < DMODEL; i += 256) {
        float xv = xr[i];
        float ln = (xv - mu) * inv * gamma[i] + beta[i];
        __nv_bfloat16 h = __float2bfloat16(ln);
        g_ahi[(size_t)row * DMODEL + i] = h;
        g_alo[(size_t)row * DMODEL + i] = __float2bfloat16(ln - __bfloat162float(h));
        __nv_bfloat16 xh = __float2bfloat16(xv);
        g_xhi[(size_t)row * DMODEL + i] = xh;
        g_xlo[(size_t)row * DMODEL + i] = __float2bfloat16(xv - __bfloat162float(xh));
    }
}

// ---------------- gate + feature map (fast-math intrinsics) ----------------
__device__ __forceinline__ float softplus_fast(float x) {
    return (x > 0.f) ? x + __logf(1.f + __expf(-x)) : __logf(1.f + __expf(x));
}

__global__ void features_kernel() {
    int idx = blockIdx.x * blockDim.x + threadIdx.x;
    if (idx >= LSEQ * DMODEL) return;
    int l = idx / DMODEL;
    int d = idx - l * DMODEL;

    const float* scr = g_semctx + (size_t)l * 3072;
    float sa = softplus_fast(scr[d]);
    float sp = scr[768 + d];
    float ca = softplus_fast(scr[1536 + d]);
    float cp = scr[2304 + d];
    float z = sa * ca * __cosf(sp - cp);
    float gate = 1.f / (1.f + __expf(-z));

    float q = g_qkv[(size_t)l * 3 * DMODEL + d];
    float k = g_qkv[(size_t)l * 3 * DMODEL + DMODEL + d] * gate;
    float v = g_qkv[(size_t)l * 3 * DMODEL + 2 * DMODEL + d];

    int h = d >> 6;
    int dh = d & 63;
    size_t o = (size_t)h * LSEQ * DHEAD + (size_t)l * DHEAD + dh;
    g_qf[o] = (q > 0.f) ? q + 1.f : __expf(q);
    g_kf[o] = (k > 0.f) ? k + 1.f : __expf(k);
    g_vv[o] = v;
}

// ---------------- phase A: per-chunk state sums ----------------
__global__ __launch_bounds__(256)
void chunk_sums_kernel() {
    int h = blockIdx.x / NCHUNK;
    int c = blockIdx.x % NCHUNK;
    const float* Kb = g_kf + (size_t)h * LSEQ * DHEAD + (size_t)c * CSIZE * DHEAD;
    const float* Vb = g_vv + (size_t)h * LSEQ * DHEAD + (size_t)c * CSIZE * DHEAD;

    __shared__ float ks[16][64];
    __shared__ float vs[16][64];
    int tid = threadIdx.x;
    int te = tid & 15;
    int td = tid >> 4;

    float acc[4][4];
    #pragma unroll
    for (int i = 0; i < 4; i++)
        #pragma unroll
        for (int j = 0; j < 4; j++) acc[i][j] = 0.f;
    float zacc[4] = {0.f, 0.f, 0.f, 0.f};

    int lr = tid >> 4;
    int lc = (tid & 15) * 4;

    for (int p0 = 0; p0 < CSIZE; p0 += 16) {
        *(float4*)&ks[lr][lc] = *(const float4*)&Kb[(size_t)(p0 + lr) * DHEAD + lc];
        *(float4*)&vs[lr][lc] = *(const float4*)&Vb[(size_t)(p0 + lr) * DHEAD + lc];
        __syncthreads();
        #pragma unroll
        for (int p = 0; p < 16; p++) {
            float kk[4], vvv[4];
            #pragma unroll
            for (int i = 0; i < 4; i++) kk[i] = ks[p][td * 4 + i];
            #pragma unroll
            for (int j = 0; j < 4; j++) vvv[j] = vs[p][te * 4 + j];
            #pragma unroll
            for (int i = 0; i < 4; i++)
                #pragma unroll
                for (int j = 0; j < 4; j++)
                    acc[i][j] = fmaf(kk[i], vvv[j], acc[i][j]);
            if (te == 0) {
                #pragma unroll
                for (int i = 0; i < 4; i++) zacc[i] += kk[i];
            }
        }
        __syncthreads();
    }

    float* Sb = g_S + (size_t)(h * NCHUNK + c) * DHEAD * DHEAD;
    #pragma unroll
    for (int i = 0; i < 4; i++)
        #pragma unroll
        for (int j = 0; j < 4; j++)
            Sb[(size_t)(td * 4 + i) * DHEAD + te * 4 + j] = acc[i][j];
    if (te == 0) {
        float* Zb = g_Z + (size_t)(h * NCHUNK + c) * DHEAD;
        #pragma unroll
        for (int i = 0; i < 4; i++) Zb[td * 4 + i] = zacc[i];
    }
}

// ---------------- phase B: exclusive scan over chunks (grid (12,4)) ----------------
__global__ __launch_bounds__(256)
void scan_states_kernel() {
    int h = blockIdx.x;
    int part = blockIdx.y;
    int tid = threadIdx.x;
    float pref[4] = {0.f, 0.f, 0.f, 0.f};
    float prefz = 0.f;

    for (int c = 0; c < NCHUNK; c++) {
        float* Sb = g_S + (size_t)(h * NCHUNK + c) * DHEAD * DHEAD + part * 1024;
        #pragma unroll
        for (int i = 0; i < 4; i++) {
            int idx = tid + i * 256;
            float cur = Sb[idx];
            Sb[idx] = pref[i];
            pref[i] += cur;
        }
        if (part == 0 && tid < DHEAD) {
            float* Zb = g_Z + (size_t)(h * NCHUNK + c) * DHEAD;
            float cur = Zb[tid];
            Zb[tid] = prefz;
            prefz += cur;
        }
    }
}

// ---------------- phase C: per-chunk causal output + bf16 split ----------------
#define SMEM_C ((2 * CSIZE * DHEAD + DHEAD * DHEAD + DHEAD) * 4)

__global__ __launch_bounds__(128)
void chunk_attn_kernel() {
    int h = blockIdx.x / NCHUNK;
    int c = blockIdx.x % NCHUNK;
    extern __shared__ float sh[];
    float* Ks = sh;
    float* Vs = Ks + CSIZE * DHEAD;
    float* Ps = Vs + CSIZE * DHEAD;
    float* Zs = Ps + DHEAD * DHEAD;

    int tid = threadIdx.x;
    size_t base = (size_t)h * LSEQ * DHEAD + (size_t)c * CSIZE * DHEAD;

    const float4* Kg = (const float4*)(g_kf + base);
    const float4* Vg = (const float4*)(g_vv + base);
    for (int j = tid; j < CSIZE * DHEAD / 4; j += 128) {
        ((float4*)Ks)[j] = Kg[j];
        ((float4*)Vs)[j] = Vg[j];
    }
    const float4* Pg = (const float4*)(g_S + (size_t)(h * NCHUNK + c) * DHEAD * DHEAD);
    for (int j = tid; j < DHEAD * DHEAD / 4; j += 128) ((float4*)Ps)[j] = Pg[j];
    const float4* Zg = (const float4*)(g_Z + (size_t)(h * NCHUNK + c) * DHEAD);
    if (tid < DHEAD / 4) ((float4*)Zs)[tid] = Zg[tid];
    __syncthreads();

    float q[DHEAD];
    {
        const float4* qp = (const float4*)(g_qf + base + (size_t)tid * DHEAD);
        #pragma unroll
        for (int i = 0; i < DHEAD / 4; i++) {
            float4 t = qp[i];
            q[4 * i + 0] = t.x; q[4 * i + 1] = t.y; q[4 * i + 2] = t.z; q[4 * i + 3] = t.w;
        }
    }

    float out[DHEAD];
    float den = 0.f;
    #pragma unroll
    for (int d = 0; d < DHEAD; d++) den = fmaf(q[d], Zs[d], den);
    #pragma unroll
    for (int e = 0; e < DHEAD; e++) out[e] = 0.f;
    #pragma unroll 8
    for (int d = 0; d < DHEAD; d++) {
        float qd = q[d];
        #pragma unroll
        for (int e = 0; e < DHEAD; e++)
            out[e] = fmaf(qd, Ps[d * DHEAD + e], out[e]);
    }

    for (int j = 0; j <= tid; j++) {
        float s = 0.f;
        const float4* kr = (const float4*)(Ks + j * DHEAD);
        #pragma unroll
        for (int i = 0; i < DHEAD / 4; i++) {
            float4 kv = kr[i];
            s = fmaf(q[4 * i + 0], kv.x, s);
            s = fmaf(q[4 * i + 1], kv.y, s);
            s = fmaf(q[4 * i + 2], kv.z, s);
            s = fmaf(q[4 * i + 3], kv.w, s);
        }
        den += s;
        const float4* vr = (const float4*)(Vs + j * DHEAD);
        #pragma unroll
        for (int i = 0; i < DHEAD / 4; i++) {
            float4 vv4 = vr[i];
            out[4 * i + 0] = fmaf(s, vv4.x, out[4 * i + 0]);
            out[4 * i + 1] = fmaf(s, vv4.y, out[4 * i + 1]);
            out[4 * i + 2] = fmaf(s, vv4.z, out[4 * i + 2]);
            out[4 * i + 3] = fmaf(s, vv4.w, out[4 * i + 3]);
        }
    }

    float inv = 1.f / (den + DEN_EPS);
    int l = c * CSIZE + tid;
    __nv_bfloat16* oh = g_athi + (size_t)l * DMODEL + h * DHEAD;
    __nv_bfloat16* ol = g_atlo + (size_t)l * DMODEL + h * DHEAD;
    #pragma unroll
    for (int e = 0; e < DHEAD; e++) {
        float v = out[e] * inv;
        __nv_bfloat16 hh = __float2bfloat16(v);
        oh[e] = hh;
        ol[e] = __float2bfloat16(v - __bfloat162float(hh));
    }
}

// ---------------- host launcher ----------------
extern "C" void kernel_launch(void* const* d_in, const int* in_sizes, int n_in,
                              void* d_out, int out_size) {
    const float* x      = (const float*)d_in[0];
    const float* W_qkv  = (const float*)d_in[1];
    const float* b_qkv  = (const float*)d_in[2];
    const float* W_sem  = (const float*)d_in[3];
    const float* b_sem  = (const float*)d_in[4];
    const float* W_ctx  = (const float*)d_in[5];
    const float* b_ctx  = (const float*)d_in[6];
    const float* W_proj = (const float*)d_in[7];
    const float* b_proj = (const float*)d_in[8];
    const float* ln_g   = (const float*)d_in[9];
    const float* ln_b   = (const float*)d_in[10];
    float* out = (float*)d_out;

    __nv_bfloat16 *p_ahi, *p_alo, *p_xhi, *p_xlo;
    __nv_bfloat16 *p_wqh, *p_wql, *p_wsh, *p_wsl, *p_wph, *p_wpl, *p_ath, *p_atl;
    float *p_bsc, *p_qkv, *p_semctx;
    cudaGetSymbolAddress((void**)&p_ahi, g_ahi);
    cudaGetSymbolAddress((void**)&p_alo, g_alo);
    cudaGetSymbolAddress((void**)&p_xhi, g_xhi);
    cudaGetSymbolAddress((void**)&p_xlo, g_xlo);
    cudaGetSymbolAddress((void**)&p_wqh, g_wqkv_hi);
    cudaGetSymbolAddress((void**)&p_wql, g_wqkv_lo);
    cudaGetSymbolAddress((void**)&p_wsh, g_wsc_hi);
    cudaGetSymbolAddress((void**)&p_wsl, g_wsc_lo);
    cudaGetSymbolAddress((void**)&p_wph, g_wpr_hi);
    cudaGetSymbolAddress((void**)&p_wpl, g_wpr_lo);
    cudaGetSymbolAddress((void**)&p_ath, g_athi);
    cudaGetSymbolAddress((void**)&p_atl, g_atlo);
    cudaGetSymbolAddress((void**)&p_bsc, g_bsc);
    cudaGetSymbolAddress((void**)&p_qkv, g_qkv);
    cudaGetSymbolAddress((void**)&p_semctx, g_semctx);

    cudaFuncSetAttribute(gemm_mma, cudaFuncAttributeMaxDynamicSharedMemorySize, GEMM_SMEM);
    cudaFuncSetAttribute(chunk_attn_kernel, cudaFuncAttributeMaxDynamicSharedMemorySize, SMEM_C);

    // weight prep (single launch) + biases + LN
    transpose_split_all<<<dim3(192, 24), dim3(32, 8)>>>(W_qkv, W_sem, W_ctx, W_proj);
    concat_bias<<<12, 256>>>(b_sem, b_ctx);
    ln_split_kernel<<<LSEQ, 256>>>(x, ln_g, ln_b);

    // tensor-core GEMMs (separate launches — R3 structure)
    gemm_mma<<<dim3(2304 / 128, LSEQ / 128), 256, GEMM_SMEM>>>(p_ahi, p_alo, p_wqh, p_wql,
                                                               b_qkv, p_qkv, 2304);
    gemm_mma<<<dim3(3072 / 128, LSEQ / 128), 256, GEMM_SMEM>>>(p_xhi, p_xlo, p_wsh, p_wsl,
                                                               p_bsc, p_semctx, 3072);

    // gate + feature map
    features_kernel<<<(LSEQ * DMODEL + 255) / 256, 256>>>();

    // chunked linear attention
    chunk_sums_kernel<<<NHEAD * NCHUNK, 256>>>();
    scan_states_kernel<<<dim3(NHEAD, 4), 256>>>();
    chunk_attn_kernel<<<NHEAD * NCHUNK, 128, SMEM_C>>>();

    // output projection (128x128 tiles — R3 structure)
    gemm_mma<<<dim3(768 / 128, LSEQ / 128), 256, GEMM_SMEM>>>(p_ath, p_atl, p_wph, p_wpl,
                                                              b_proj, out, 768);
}

// round 7
// speedup vs baseline: 2.1680x; 1.4163x over previous
#include <cuda_runtime.h>
#include <cuda_fp16.h>
#include <math.h>
#include <stdint.h>

// ---------------- problem constants ----------------
#define LSEQ 2048
#define DMODEL 768
#define KDIM 768
#define NHEAD 12
#define DHEAD 64
#define NCHUNK 16
#define CSIZE 128
#define LN_EPS 1e-5f
#define DEN_EPS 1e-6f

// ---------------- scratch (device globals) ----------------
__device__ __align__(128) __half g_a   [LSEQ * DMODEL];   // LN(x) fp16
__device__ __align__(128) __half g_x   [LSEQ * DMODEL];   // x fp16
__device__ __align__(128) __half g_wqkv[2304 * KDIM];     // W_qkv^T fp16
__device__ __align__(128) __half g_wsc [3072 * KDIM];     // [W_sem;W_ctx]^T fp16
__device__ __align__(128) __half g_wpr [768 * KDIM];      // W_proj^T fp16
__device__ __align__(128) __half g_at  [LSEQ * DMODEL];   // attn out fp16
__device__ __align__(128) float g_bsc[3072];
__device__ __align__(128) float g_qkv[LSEQ * 3 * DMODEL];
__device__ __align__(128) float g_semctx[LSEQ * 3072];
__device__ float g_qf[NHEAD * LSEQ * DHEAD];
__device__ float g_kf[NHEAD * LSEQ * DHEAD];
__device__ float g_vv[NHEAD * LSEQ * DHEAD];
__device__ float g_S [NHEAD * NCHUNK * DHEAD * DHEAD];
__device__ float g_Z [NHEAD * NCHUNK * DHEAD];

// ---------------- PTX helpers (family-portable only) ----------------
__device__ __forceinline__ uint32_t smem_u32(const void* p) {
    uint32_t a;
    asm("{ .reg .u64 t; cvta.to.shared.u64 t, %1; cvt.u32.u64 %0, t; }" : "=r"(a) : "l"(p));
    return a;
}
__device__ __forceinline__ void cp_async16(uint32_t dst, const void* src) {
    asm volatile("cp.async.cg.shared.global [%0], [%1], 16;" :: "r"(dst), "l"(src));
}
__device__ __forceinline__ void cp_commit() {
    asm volatile("cp.async.commit_group;" ::: "memory");
}
__device__ __forceinline__ void cp_wait2() {
    asm volatile("cp.async.wait_group 2;" ::: "memory");
}
#define LDSM4(r0, r1, r2, r3, a) \
    asm volatile("ldmatrix.sync.aligned.m8n8.x4.shared.b16 {%0,%1,%2,%3}, [%4];" \
                 : "=r"(r0), "=r"(r1), "=r"(r2), "=r"(r3) : "r"(a))
#define MMAF16(d, a0, a1, a2, a3, b0, b1) \
    asm volatile("mma.sync.aligned.m16n8k16.row.col.f32.f16.f16.f32 " \
                 "{%0,%1,%2,%3}, {%4,%5,%6,%7}, {%8,%9}, {%0,%1,%2,%3};" \
                 : "+f"((d)[0]), "+f"((d)[1]), "+f"((d)[2]), "+f"((d)[3]) \
                 : "r"(a0), "r"(a1), "r"(a2), "r"(a3), "r"(b0), "r"(b1))

// ---------------- GEMM: C[2048,Ntot] = A @ B^T + bias (fp16 single pass) ----------------
#define BK 32
#define ROWB 80                       // padded smem row stride (bytes)
#define TILEB (128 * ROWB)            // 10240 B per 128x32 tile
#define STAGEB (2 * TILEB)            // A, B
#define NSTAGE 4
#define GEMM_SMEM (NSTAGE * STAGEB)   // 81920 B
#define NKT (KDIM / BK)               // 24

__device__ __forceinline__ void g_load_stage(
    uint32_t smem_base, int s, int tid,
    const __half* a, const __half* b)
{
    uint32_t stb = smem_base + (uint32_t)(s & (NSTAGE - 1)) * STAGEB;
    int kk = s * BK;
    #pragma unroll
    for (int t = 0; t < 2; t++) {
        const __half* base = t ? b : a;
        #pragma unroll
        for (int i = 0; i < 2; i++) {
            int c = tid + i * 256;          // 0..511
            int r = c >> 2;
            int seg = c & 3;
            cp_async16(stb + (uint32_t)t * TILEB + (uint32_t)(r * ROWB + seg * 16),
                       base + (size_t)r * KDIM + kk + seg * 8);
        }
    }
}

__global__ __launch_bounds__(256, 2)
void gemm_mma(const __half* __restrict__ A, const __half* __restrict__ BT,
              const float* __restrict__ bias, float* __restrict__ C, int Ntot)
{
    extern __shared__ __align__(128) char smem[];
    const int tid = threadIdx.x;
    const int wid = tid >> 5;
    const int lane = tid & 31;
    const int wm = wid & 1;        // M: 2 x 64
    const int wn = wid >> 1;       // N: 4 x 32
    const int bx = blockIdx.x, by = blockIdx.y;

    uint32_t smem_base = smem_u32(smem);

    const __half* a = A + (size_t)by * 128 * KDIM;
    const __half* b = BT + (size_t)bx * 128 * KDIM;

    float acc[4][4][4];
    #pragma unroll
    for (int i = 0; i < 4; i++)
        #pragma unroll
        for (int j = 0; j < 4; j++)
            #pragma unroll
            for (int t = 0; t < 4; t++) acc[i][j][t] = 0.f;

    const uint32_t a_row = (uint32_t)(lane & 15);
    const uint32_t a_byt = (uint32_t)((lane >> 4) * 16);
    const uint32_t b_row = (uint32_t)((lane & 7) + ((lane >> 4) << 3));
    const uint32_t b_byt = (uint32_t)(((lane >> 3) & 1) * 16);

    // prologue: 3 stages in flight
    g_load_stage(smem_base, 0, tid, a, b); cp_commit();
    g_load_stage(smem_base, 1, tid, a, b); cp_commit();
    g_load_stage(smem_base, 2, tid, a, b); cp_commit();

    for (int s = 0; s < NKT; s++) {
        cp_wait2();                 // group s retired (<=2 outstanding)
        __syncthreads();            // single barrier per stage
        if (s + 3 < NKT) g_load_stage(smem_base, s + 3, tid, a, b);
        cp_commit();

        uint32_t stb = smem_base + (uint32_t)(s & (NSTAGE - 1)) * STAGEB;
        #pragma unroll
        for (int k16 = 0; k16 < 2; k16++) {
            const uint32_t koff = (uint32_t)(k16 * 32);
            uint32_t af[4][4];
            #pragma unroll
            for (int mt = 0; mt < 4; mt++) {
                uint32_t addr = stb + (uint32_t)(wm * 64 + mt * 16 + a_row) * ROWB
                              + koff + a_byt;
                LDSM4(af[mt][0], af[mt][1], af[mt][2], af[mt][3], addr);
            }
            uint32_t bf[2][4];
            #pragma unroll
            for (int nb = 0; nb < 2; nb++) {
                uint32_t addr = stb + TILEB + (uint32_t)(wn * 32 + nb * 16 + b_row) * ROWB
                              + koff + b_byt;
                LDSM4(bf[nb][0], bf[nb][1], bf[nb][2], bf[nb][3], addr);
            }
            #pragma unroll
            for (int mt = 0; mt < 4; mt++)
                #pragma unroll
                for (int nt = 0; nt < 4; nt++)
                    MMAF16(acc[mt][nt],
                           af[mt][0], af[mt][1], af[mt][2], af[mt][3],
                           bf[nt >> 1][(nt & 1) * 2], bf[nt >> 1][(nt & 1) * 2 + 1]);
        }
    }

    int r0 = by * 128 + wm * 64 + (lane >> 2);
    int c0 = bx * 128 + wn * 32 + (lane & 3) * 2;
    #pragma unroll
    for (int mt = 0; mt < 4; mt++) {
        #pragma unroll
        for (int nt = 0; nt < 4; nt++) {
            int r = r0 + mt * 16;
            int c = c0 + nt * 8;
            float2 v0 = { acc[mt][nt][0] + bias[c], acc[mt][nt][1] + bias[c + 1] };
            float2 v1 = { acc[mt][nt][2] + bias[c], acc[mt][nt][3] + bias[c + 1] };
            *(float2*)&C[(size_t)r * Ntot + c] = v0;
            *(float2*)&C[(size_t)(r + 8) * Ntot + c] = v1;
        }
    }
}

// ---------------- merged weight transpose + fp16 convert (one launch) ----------------
__global__ void transpose_split_all(const float* __restrict__ Wq,
                                    const float* __restrict__ Ws,
                                    const float* __restrict__ Wc,
                                    const float* __restrict__ Wp)
{
    __shared__ float tile[32][33];
    int bx = blockIdx.x;
    const float* W; int N, rowOff;
    __half* oT;
    if (bx < 72)       { W = Wq; N = 2304; rowOff = 0;    oT = g_wqkv; }
    else if (bx < 120) { W = Ws; N = 1536; rowOff = 0;    oT = g_wsc;  bx -= 72; }
    else if (bx < 168) { W = Wc; N = 1536; rowOff = 1536; oT = g_wsc;  bx -= 120; }
    else               { W = Wp; N = 768;  rowOff = 0;    oT = g_wpr;  bx -= 168; }

    int n0 = bx * 32, k0 = blockIdx.y * 32;
    int tx = threadIdx.x, ty = threadIdx.y;   // (32, 8)
    #pragma unroll
    for (int i = 0; i < 4; i++)
        tile[ty + i * 8][tx] = W[(size_t)(k0 + ty + i * 8) * N + n0 + tx];
    __syncthreads();
    #pragma unroll
    for (int i = 0; i < 4; i++) {
        int n = ty + i * 8;
        oT[(size_t)(rowOff + n0 + n) * KDIM + k0 + tx] = __float2half(tile[tx][n]);
    }
}

__global__ void concat_bias(const float* __restrict__ bs, const float* __restrict__ bc) {
    int i = blockIdx.x * 256 + threadIdx.x;
    if (i < 1536) g_bsc[i] = bs[i];
    else if (i < 3072) g_bsc[i] = bc[i - 1536];
}

// ---------------- LayerNorm + fp16 convert (also converts raw x) ----------------
__global__ void ln_split_kernel(const float* __restrict__ x,
                                const float* __restrict__ gamma,
                                const float* __restrict__ beta) {
    int row = blockIdx.x;
    const float* xr = x + (size_t)row * DMODEL;
    int tid = threadIdx.x;
    __shared__ float red[8];

    float s = 0.f;
    for (int i = tid; i < DMODEL; i += 256) s += xr[i];
    #pragma unroll
    for (int o = 16; o > 0; o >>= 1) s += __shfl_down_sync(0xffffffffu, s, o);
    if ((tid & 31) == 0) red[tid >> 5] = s;
    __syncthreads();
    if (tid < 8) {
        s = red[tid];
        #pragma unroll
        for (int o = 4; o > 0; o >>= 1) s += __shfl_down_sync(0xffu, s, o);
        if (tid == 0) red[0] = s;
    }
    __syncthreads();
    float mu = red[0] * (1.f / DMODEL);
    __syncthreads();

    float v = 0.f;
    for (int i = tid; i < DMODEL; i += 256) { float d = xr[i] - mu; v += d * d; }
    #pragma unroll
    for (int o = 16; o > 0; o >>= 1) v += __shfl_down_sync(0xffffffffu, v, o);
    if ((tid & 31) == 0) red[tid >> 5] = v;
    __syncthreads();
    if (tid < 8) {
        v = red[tid];
        #pragma unroll
        for (int o = 4; o > 0; o >>= 1) v += __shfl_down_sync(0xffu, v, o);
        if (tid == 0) red[0] = v;
    }
    __syncthreads();
    float inv = rsqrtf(red[0] * (1.f / DMODEL) + LN_EPS);

    for (int i = tid; i < DMODEL; i += 256) {
        float xv = xr[i];
        float ln = (xv - mu) * inv * gamma[i] + beta[i];
        g_a[(size_t)row * DMODEL + i] = __float2half(ln);
        g_x[(size_t)row * DMODEL + i] = __float2half(xv);
    }
}

// ---------------- gate + feature map (fast-math intrinsics) ----------------
__device__ __forceinline__ float softplus_fast(float x) {
    return (x > 0.f) ? x + __logf(1.f + __expf(-x)) : __logf(1.f + __expf(x));
}

__global__ void features_kernel() {
    int idx = blockIdx.x * blockDim.x + threadIdx.x;
    if (idx >= LSEQ * DMODEL) return;
    int l = idx / DMODEL;
    int d = idx - l * DMODEL;

    const float* scr = g_semctx + (size_t)l * 3072;
    float sa = softplus_fast(scr[d]);
    float sp = scr[768 + d];
    float ca = softplus_fast(scr[1536 + d]);
    float cp = scr[2304 + d];
    float z = sa * ca * __cosf(sp - cp);
    float gate = 1.f / (1.f + __expf(-z));

    float q = g_qkv[(size_t)l * 3 * DMODEL + d];
    float k = g_qkv[(size_t)l * 3 * DMODEL + DMODEL + d] * gate;
    float v = g_qkv[(size_t)l * 3 * DMODEL + 2 * DMODEL + d];

    int h = d >> 6;
    int dh = d & 63;
    size_t o = (size_t)h * LSEQ * DHEAD + (size_t)l * DHEAD + dh;
    g_qf[o] = (q > 0.f) ? q + 1.f : __expf(q);
    g_kf[o] = (k > 0.f) ? k + 1.f : __expf(k);
    g_vv[o] = v;
}

// ---------------- phase A: per-chunk state sums ----------------
__global__ __launch_bounds__(256)
void chunk_sums_kernel() {
    int h = blockIdx.x / NCHUNK;
    int c = blockIdx.x % NCHUNK;
    const float* Kb = g_kf + (size_t)h * LSEQ * DHEAD + (size_t)c * CSIZE * DHEAD;
    const float* Vb = g_vv + (size_t)h * LSEQ * DHEAD + (size_t)c * CSIZE * DHEAD;

    __shared__ float ks[16][64];
    __shared__ float vs[16][64];
    int tid = threadIdx.x;
    int te = tid & 15;
    int td = tid >> 4;

    float acc[4][4];
    #pragma unroll
    for (int i = 0; i < 4; i++)
        #pragma unroll
        for (int j = 0; j < 4; j++) acc[i][j] = 0.f;
    float zacc[4] = {0.f, 0.f, 0.f, 0.f};

    int lr = tid >> 4;
    int lc = (tid & 15) * 4;

    for (int p0 = 0; p0 < CSIZE; p0 += 16) {
        *(float4*)&ks[lr][lc] = *(const float4*)&Kb[(size_t)(p0 + lr) * DHEAD + lc];
        *(float4*)&vs[lr][lc] = *(const float4*)&Vb[(size_t)(p0 + lr) * DHEAD + lc];
        __syncthreads();
        #pragma unroll
        for (int p = 0; p < 16; p++) {
            float kk[4], vvv[4];
            #pragma unroll
            for (int i = 0; i < 4; i++) kk[i] = ks[p][td * 4 + i];
            #pragma unroll
            for (int j = 0; j < 4; j++) vvv[j] = vs[p][te * 4 + j];
            #pragma unroll
            for (int i = 0; i < 4; i++)
                #pragma unroll
                for (int j = 0; j < 4; j++)
                    acc[i][j] = fmaf(kk[i], vvv[j], acc[i][j]);
            if (te == 0) {
                #pragma unroll
                for (int i = 0; i < 4; i++) zacc[i] += kk[i];
            }
        }
        __syncthreads();
    }

    float* Sb = g_S + (size_t)(h * NCHUNK + c) * DHEAD * DHEAD;
    #pragma unroll
    for (int i = 0; i < 4; i++)
        #pragma unroll
        for (int j = 0; j < 4; j++)
            Sb[(size_t)(td * 4 + i) * DHEAD + te * 4 + j] = acc[i][j];
    if (te == 0) {
        float* Zb = g_Z + (size_t)(h * NCHUNK + c) * DHEAD;
        #pragma unroll
        for (int i = 0; i < 4; i++) Zb[td * 4 + i] = zacc[i];
    }
}

// ---------------- phase B: exclusive scan over chunks (grid (12,4)) ----------------
__global__ __launch_bounds__(256)
void scan_states_kernel() {
    int h = blockIdx.x;
    int part = blockIdx.y;
    int tid = threadIdx.x;
    float pref[4] = {0.f, 0.f, 0.f, 0.f};
    float prefz = 0.f;

    for (int c = 0; c < NCHUNK; c++) {
        float* Sb = g_S + (size_t)(h * NCHUNK + c) * DHEAD * DHEAD + part * 1024;
        #pragma unroll
        for (int i = 0; i < 4; i++) {
            int idx = tid + i * 256;
            float cur = Sb[idx];
            Sb[idx] = pref[i];
            pref[i] += cur;
        }
        if (part == 0 && tid < DHEAD) {
            float* Zb = g_Z + (size_t)(h * NCHUNK + c) * DHEAD;
            float cur = Zb[tid];
            Zb[tid] = prefz;
            prefz += cur;
        }
    }
}

// ---------------- phase C: per-chunk causal output (K,V in smem; P,Z via L1 broadcast) ----------------
#define SMEM_C (2 * CSIZE * DHEAD * 4)   // 65536 B -> 3 CTAs/SM

__global__ __launch_bounds__(128)
void chunk_attn_kernel() {
    int h = blockIdx.x / NCHUNK;
    int c = blockIdx.x % NCHUNK;
    extern __shared__ float sh[];
    float* Ks = sh;
    float* Vs = Ks + CSIZE * DHEAD;

    int tid = threadIdx.x;
    size_t base = (size_t)h * LSEQ * DHEAD + (size_t)c * CSIZE * DHEAD;

    const float4* Kg = (const float4*)(g_kf + base);
    const float4* Vg = (const float4*)(g_vv + base);
    for (int j = tid; j < CSIZE * DHEAD / 4; j += 128) {
        ((float4*)Ks)[j] = Kg[j];
        ((float4*)Vs)[j] = Vg[j];
    }
    __syncthreads();

    float q[DHEAD];
    {
        const float4* qp = (const float4*)(g_qf + base + (size_t)tid * DHEAD);
        #pragma unroll
        for (int i = 0; i < DHEAD / 4; i++) {
            float4 t = qp[i];
            q[4 * i + 0] = t.x; q[4 * i + 1] = t.y; q[4 * i + 2] = t.z; q[4 * i + 3] = t.w;
        }
    }

    const float* Pg = g_S + (size_t)(h * NCHUNK + c) * DHEAD * DHEAD;
    const float* Zg = g_Z + (size_t)(h * NCHUNK + c) * DHEAD;

    float out[DHEAD];
    float den = 0.f;
    #pragma unroll
    for (int d = 0; d < DHEAD; d++) den = fmaf(q[d], __ldg(&Zg[d]), den);
    #pragma unroll
    for (int e = 0; e < DHEAD; e++) out[e] = 0.f;
    // prefix: out += q @ P  (uniform addresses -> L1 broadcast)
    #pragma unroll 4
    for (int d = 0; d < DHEAD; d++) {
        float qd = q[d];
        const float4* pr = (const float4*)(Pg + d * DHEAD);
        #pragma unroll
        for (int i = 0; i < DHEAD / 4; i++) {
            float4 p = __ldg(&pr[i]);
            out[4 * i + 0] = fmaf(qd, p.x, out[4 * i + 0]);
            out[4 * i + 1] = fmaf(qd, p.y, out[4 * i + 1]);
            out[4 * i + 2] = fmaf(qd, p.z, out[4 * i + 2]);
            out[4 * i + 3] = fmaf(qd, p.w, out[4 * i + 3]);
        }
    }

    // intra-chunk causal (4-way split dot for ILP)
    for (int j = 0; j <= tid; j++) {
        const float4* kr = (const float4*)(Ks + j * DHEAD);
        float s0 = 0.f, s1 = 0.f, s2 = 0.f, s3 = 0.f;
        #pragma unroll
        for (int i = 0; i < DHEAD / 4; i += 4) {
            float4 k0 = kr[i], k1 = kr[i + 1], k2 = kr[i + 2], k3 = kr[i + 3];
            s0 = fmaf(q[4 * i + 0], k0.x, s0); s0 = fmaf(q[4 * i + 1], k0.y, s0);
            s0 = fmaf(q[4 * i + 2], k0.z, s0); s0 = fmaf(q[4 * i + 3], k0.w, s0);
            s1 = fmaf(q[4 * i + 4], k1.x, s1); s1 = fmaf(q[4 * i + 5], k1.y, s1);
            s1 = fmaf(q[4 * i + 6], k1.z, s1); s1 = fmaf(q[4 * i + 7], k1.w, s1);
            s2 = fmaf(q[4 * i + 8], k2.x, s2); s2 = fmaf(q[4 * i + 9], k2.y, s2);
            s2 = fmaf(q[4 * i + 10], k2.z, s2); s2 = fmaf(q[4 * i + 11], k2.w, s2);
            s3 = fmaf(q[4 * i + 12], k3.x, s3); s3 = fmaf(q[4 * i + 13], k3.y, s3);
            s3 = fmaf(q[4 * i + 14], k3.z, s3); s3 = fmaf(q[4 * i + 15], k3.w, s3);
        }
        float s = (s0 + s1) + (s2 + s3);
        den += s;
        const float4* vr = (const float4*)(Vs + j * DHEAD);
        #pragma unroll
        for (int i = 0; i < DHEAD / 4; i++) {
            float4 vv4 = vr[i];
            out[4 * i + 0] = fmaf(s, vv4.x, out[4 * i + 0]);
            out[4 * i + 1] = fmaf(s, vv4.y, out[4 * i + 1]);
            out[4 * i + 2] = fmaf(s, vv4.z, out[4 * i + 2]);
            out[4 * i + 3] = fmaf(s, vv4.w, out[4 * i + 3]);
        }
    }

    float inv = 1.f / (den + DEN_EPS);
    int l = c * CSIZE + tid;
    __half* op = g_at + (size_t)l * DMODEL + h * DHEAD;
    #pragma unroll
    for (int e = 0; e < DHEAD; e += 2) {
        __half2 hv = __floats2half2_rn(out[e] * inv, out[e + 1] * inv);
        *(__half2*)&op[e] = hv;
    }
}

// ---------------- host launcher ----------------
extern "C" void kernel_launch(void* const* d_in, const int* in_sizes, int n_in,
                              void* d_out, int out_size) {
    const float* x      = (const float*)d_in[0];
    const float* W_qkv  = (const float*)d_in[1];
    const float* b_qkv  = (const float*)d_in[2];
    const float* W_sem  = (const float*)d_in[3];
    const float* b_sem  = (const float*)d_in[4];
    const float* W_ctx  = (const float*)d_in[5];
    const float* b_ctx  = (const float*)d_in[6];
    const float* W_proj = (const float*)d_in[7];
    const float* b_proj = (const float*)d_in[8];
    const float* ln_g   = (const float*)d_in[9];
    const float* ln_b   = (const float*)d_in[10];
    float* out = (float*)d_out;

    __half *p_a, *p_x, *p_wq, *p_ws, *p_wp, *p_at;
    float *p_bsc, *p_qkv, *p_semctx;
    cudaGetSymbolAddress((void**)&p_a, g_a);
    cudaGetSymbolAddress((void**)&p_x, g_x);
    cudaGetSymbolAddress((void**)&p_wq, g_wqkv);
    cudaGetSymbolAddress((void**)&p_ws, g_wsc);
    cudaGetSymbolAddress((void**)&p_wp, g_wpr);
    cudaGetSymbolAddress((void**)&p_at, g_at);
    cudaGetSymbolAddress((void**)&p_bsc, g_bsc);
    cudaGetSymbolAddress((void**)&p_qkv, g_qkv);
    cudaGetSymbolAddress((void**)&p_semctx, g_semctx);

    cudaFuncSetAttribute(gemm_mma, cudaFuncAttributeMaxDynamicSharedMemorySize, GEMM_SMEM);
    cudaFuncSetAttribute(chunk_attn_kernel, cudaFuncAttributeMaxDynamicSharedMemorySize, SMEM_C);

    // weight prep (single launch) + biases + LN
    transpose_split_all<<<dim3(192, 24), dim3(32, 8)>>>(W_qkv, W_sem, W_ctx, W_proj);
    concat_bias<<<12, 256>>>(b_sem, b_ctx);
    ln_split_kernel<<<LSEQ, 256>>>(x, ln_g, ln_b);

    // fp16 tensor-core GEMMs
    gemm_mma<<<dim3(2304 / 128, LSEQ / 128), 256, GEMM_SMEM>>>(p_a, p_wq, b_qkv, p_qkv, 2304);
    gemm_mma<<<dim3(3072 / 128, LSEQ / 128), 256, GEMM_SMEM>>>(p_x, p_ws, p_bsc, p_semctx, 3072);

    // gate + feature map
    features_kernel<<<(LSEQ * DMODEL + 255) / 256, 256>>>();

    // chunked linear attention
    chunk_sums_kernel<<<NHEAD * NCHUNK, 256>>>();
    scan_states_kernel<<<dim3(NHEAD, 4), 256>>>();
    chunk_attn_kernel<<<NHEAD * NCHUNK, 128, SMEM_C>>>();

    // output projection
    gemm_mma<<<dim3(768 / 128, LSEQ / 128), 256, GEMM_SMEM>>>(p_at, p_wp, b_proj, out, 768);
}